// round 3
// baseline (speedup 1.0000x reference)
#include <cuda_runtime.h>
#include <cstdint>

// Problem constants
#define BATCH 64
#define TLEN  128
#define NS    100
#define AD    16
#define HD    120
#define G4    480          // 4*HD
#define NSEQ  (BATCH * NS) // 6400
#define TAU_INV 0.2f

// LSTM kernel tiling
#define SEQ_PB 48
#define NBLK   ((NSEQ + SEQ_PB - 1) / SEQ_PB)   // 134
#define NTHR   480                               // 16 seq-groups x 30 j-groups

// Scratch (device globals; no dynamic allocation allowed)
__device__ float g_s[NSEQ];                    // scores per sequence
__device__ float g_phat[BATCH * NS * NS];      // relaxed permutation matrices
__device__ float g_z1[BATCH * 256];            // MLP hidden

__device__ __forceinline__ float sigf(float x) {
    return __fdividef(1.0f, 1.0f + __expf(-x));
}
__device__ __forceinline__ float tanhf_fast(float x) {
    return 2.0f * __fdividef(1.0f, 1.0f + __expf(-2.0f * x)) - 1.0f;
}

// ---------------------------------------------------------------------------
// Kernel 1: LSTM over all 6400 sequences + score head.
// Block: 48 sequences, 480 threads.
//   sg = tid & 15  -> 3 local seqs: sg, sg+16, sg+32
//   jg = tid >> 4  -> hidden units j0..j0+3 (j0 = 4*jg), all 4 gate types
// h state in SMEM (k-major); c state in registers; W streamed from L2.
// ---------------------------------------------------------------------------
__global__ void __launch_bounds__(NTHR, 1)
lstm_kernel(const float* __restrict__ x,
            const float* __restrict__ Wih,
            const float* __restrict__ Whh,
            const float* __restrict__ bih,
            const float* __restrict__ bhh,
            const float* __restrict__ wlin,
            const float* __restrict__ blin)
{
    __shared__ float h_sm[HD][SEQ_PB];     // 23040 B
    __shared__ float x_sm[AD][SEQ_PB];     //  3072 B
    __shared__ float bias_sm[G4];          //  1920 B

    const int tid = threadIdx.x;
    const int sg  = tid & 15;
    const int jg  = tid >> 4;              // 0..29
    const int j0  = jg * 4;
    const int n0  = blockIdx.x * SEQ_PB;

    // init shared
    for (int i = tid; i < HD * SEQ_PB; i += NTHR) (&h_sm[0][0])[i] = 0.0f;
    for (int i = tid; i < AD * SEQ_PB; i += NTHR) (&x_sm[0][0])[i] = 0.0f;
    if (tid < G4) bias_sm[tid] = bih[tid] + bhh[tid];

    // per-thread x loader setup (threads < 192 load x_t each step)
    size_t xbase = 0;
    bool xvalid = false;
    int xl = 0, xa4 = 0;
    if (tid < 192) {
        xl  = tid >> 2;          // local seq 0..47
        xa4 = tid & 3;           // float4 index within A=16
        int n = n0 + xl;
        if (n < NSEQ) {
            int b  = n / NS;
            int st = n % NS;
            xbase  = ((size_t)b * TLEN * NS + st) * AD + xa4 * 4;
            xvalid = true;
        }
    }

    float c[4][3];
    #pragma unroll
    for (int jj = 0; jj < 4; ++jj)
        #pragma unroll
        for (int ss = 0; ss < 3; ++ss) c[jj][ss] = 0.0f;

    __syncthreads();

    for (int t = 0; t < TLEN; ++t) {
        // ---- load x_t into x_sm (transposed, k-major) ----
        if (xvalid) {
            float4 v = *(const float4*)&x[xbase + (size_t)t * (NS * AD)];
            x_sm[xa4 * 4 + 0][xl] = v.x;
            x_sm[xa4 * 4 + 1][xl] = v.y;
            x_sm[xa4 * 4 + 2][xl] = v.z;
            x_sm[xa4 * 4 + 3][xl] = v.w;
        }

        // ---- init accumulators with bias ----
        float acc[4][4][3];
        #pragma unroll
        for (int q = 0; q < 4; ++q)
            #pragma unroll
            for (int jj = 0; jj < 4; ++jj) {
                float bv = bias_sm[q * HD + j0 + jj];
                acc[q][jj][0] = bv; acc[q][jj][1] = bv; acc[q][jj][2] = bv;
            }

        // ---- recurrent part: acc += W_hh[g,:] . h  (K = 120) ----
        #pragma unroll 2
        for (int kk = 0; kk < HD / 4; ++kk) {
            const int kb = kk * 4;
            float a[4][3];
            #pragma unroll
            for (int dk = 0; dk < 4; ++dk) {
                a[dk][0] = h_sm[kb + dk][sg];
                a[dk][1] = h_sm[kb + dk][sg + 16];
                a[dk][2] = h_sm[kb + dk][sg + 32];
            }
            #pragma unroll
            for (int q = 0; q < 4; ++q) {
                float4 w[4];
                #pragma unroll
                for (int jj = 0; jj < 4; ++jj)
                    w[jj] = *(const float4*)&Whh[(q * HD + j0 + jj) * HD + kb];
                #pragma unroll
                for (int jj = 0; jj < 4; ++jj) {
                    float wx[4] = {w[jj].x, w[jj].y, w[jj].z, w[jj].w};
                    #pragma unroll
                    for (int dk = 0; dk < 4; ++dk) {
                        acc[q][jj][0] = fmaf(wx[dk], a[dk][0], acc[q][jj][0]);
                        acc[q][jj][1] = fmaf(wx[dk], a[dk][1], acc[q][jj][1]);
                        acc[q][jj][2] = fmaf(wx[dk], a[dk][2], acc[q][jj][2]);
                    }
                }
            }
        }

        __syncthreads();   // x_sm written by all; h_sm reads done by all

        // ---- input part: acc += W_ih[g,:] . x_t  (K = 16) ----
        #pragma unroll
        for (int kk = 0; kk < AD / 4; ++kk) {
            const int kb = kk * 4;
            float a[4][3];
            #pragma unroll
            for (int dk = 0; dk < 4; ++dk) {
                a[dk][0] = x_sm[kb + dk][sg];
                a[dk][1] = x_sm[kb + dk][sg + 16];
                a[dk][2] = x_sm[kb + dk][sg + 32];
            }
            #pragma unroll
            for (int q = 0; q < 4; ++q) {
                float4 w[4];
                #pragma unroll
                for (int jj = 0; jj < 4; ++jj)
                    w[jj] = *(const float4*)&Wih[(q * HD + j0 + jj) * AD + kb];
                #pragma unroll
                for (int jj = 0; jj < 4; ++jj) {
                    float wx[4] = {w[jj].x, w[jj].y, w[jj].z, w[jj].w};
                    #pragma unroll
                    for (int dk = 0; dk < 4; ++dk) {
                        acc[q][jj][0] = fmaf(wx[dk], a[dk][0], acc[q][jj][0]);
                        acc[q][jj][1] = fmaf(wx[dk], a[dk][1], acc[q][jj][1]);
                        acc[q][jj][2] = fmaf(wx[dk], a[dk][2], acc[q][jj][2]);
                    }
                }
            }
        }

        // ---- gate activations + state update (gate order: i, f, g, o) ----
        #pragma unroll
        for (int jj = 0; jj < 4; ++jj) {
            #pragma unroll
            for (int ss = 0; ss < 3; ++ss) {
                float ig = sigf(acc[0][jj][ss]);
                float fg = sigf(acc[1][jj][ss]);
                float gg = tanhf_fast(acc[2][jj][ss]);
                float og = sigf(acc[3][jj][ss]);
                float cn = fg * c[jj][ss] + ig * gg;
                c[jj][ss] = cn;
                h_sm[j0 + jj][sg + ss * 16] = og * tanhf_fast(cn);
            }
        }
        __syncthreads();   // h_sm fully updated for next step
    }

    // ---- score head: s[n] = h . w_lin + b_lin ----
    if (tid < SEQ_PB) {
        int n = n0 + tid;
        if (n < NSEQ) {
            float s = blin[0];
            #pragma unroll 4
            for (int j = 0; j < HD; ++j) s = fmaf(h_sm[j][tid], wlin[j], s);
            g_s[n] = s;
        }
    }
}

// ---------------------------------------------------------------------------
// Kernel 2: NeuralSort relaxed permutation.
// p_hat[b,r,c] = softmax_c( (s_c * (99 - 2r) - rowsum_c) / TAU )
// One block per batch, 128 threads (warp-per-row).
// ---------------------------------------------------------------------------
__global__ void sort_kernel()
{
    const int b   = blockIdx.x;
    const int tid = threadIdx.x;
    __shared__ float s_sm[NS];
    __shared__ float rs_sm[NS];

    if (tid < NS) s_sm[tid] = g_s[b * NS + tid];
    __syncthreads();

    if (tid < NS) {
        float si = s_sm[tid], r = 0.0f;
        #pragma unroll 4
        for (int j = 0; j < NS; ++j) r += fabsf(si - s_sm[j]);
        rs_sm[tid] = r;
    }
    __syncthreads();

    const int warp = tid >> 5, lane = tid & 31;
    for (int r = warp; r < NS; r += 4) {
        float scal = 99.0f - 2.0f * (float)r;
        float v[4];
        float mx = -1e30f;
        #pragma unroll
        for (int i = 0; i < 4; ++i) {
            int cidx = lane + i * 32;
            v[i] = (cidx < NS) ? (s_sm[cidx] * scal - rs_sm[cidx]) * TAU_INV : -1e30f;
            mx = fmaxf(mx, v[i]);
        }
        #pragma unroll
        for (int o = 16; o; o >>= 1) mx = fmaxf(mx, __shfl_xor_sync(0xffffffffu, mx, o));
        float sum = 0.0f;
        #pragma unroll
        for (int i = 0; i < 4; ++i) {
            int cidx = lane + i * 32;
            v[i] = (cidx < NS) ? __expf(v[i] - mx) : 0.0f;
            sum += v[i];
        }
        #pragma unroll
        for (int o = 16; o; o >>= 1) sum += __shfl_xor_sync(0xffffffffu, sum, o);
        float inv = __fdividef(1.0f, sum);
        #pragma unroll
        for (int i = 0; i < 4; ++i) {
            int cidx = lane + i * 32;
            if (cidx < NS) g_phat[((size_t)b * NS + r) * NS + cidx] = v[i] * inv;
        }
    }
}

// ---------------------------------------------------------------------------
// Kernel 3: z1 = relu(p_hat_flat @ W2^T + b2).  One block per batch.
// p_hat row (10000 floats) staged in smem; warp per output unit.
// ---------------------------------------------------------------------------
__global__ void mlp1_kernel(const float* __restrict__ W2,
                            const float* __restrict__ b2)
{
    const int b   = blockIdx.x;
    const int tid = threadIdx.x;   // 256
    const int warp = tid >> 5, lane = tid & 31;
    __shared__ float p_sm[NS * NS];   // 40000 B

    const float* __restrict__ pr = g_phat + (size_t)b * (NS * NS);
    for (int i = tid; i < NS * NS; i += 256) p_sm[i] = pr[i];
    __syncthreads();

    for (int u = warp; u < 256; u += 8) {
        const float* __restrict__ w = W2 + (size_t)u * (NS * NS);
        float acc = 0.0f;
        for (int m = lane * 4; m < NS * NS; m += 32 * 4) {
            float4 wv = *(const float4*)&w[m];
            float4 pv = *(const float4*)&p_sm[m];
            acc = fmaf(wv.x, pv.x, acc);
            acc = fmaf(wv.y, pv.y, acc);
            acc = fmaf(wv.z, pv.z, acc);
            acc = fmaf(wv.w, pv.w, acc);
        }
        #pragma unroll
        for (int o = 16; o; o >>= 1) acc += __shfl_xor_sync(0xffffffffu, acc, o);
        if (lane == 0) g_z1[b * 256 + u] = fmaxf(acc + b2[u], 0.0f);
    }
}

// ---------------------------------------------------------------------------
// Kernel 4: out = softmax(z1 @ W3^T + b3).  One block per batch, 128 threads.
// ---------------------------------------------------------------------------
__global__ void mlp2_kernel(const float* __restrict__ W3,
                            const float* __restrict__ b3,
                            float* __restrict__ out)
{
    const int b   = blockIdx.x;
    const int tid = threadIdx.x;   // 128
    __shared__ float z_sm[256];
    __shared__ float v_sm[NS];
    __shared__ float red[2];

    for (int i = tid; i < 256; i += 128) z_sm[i] = g_z1[b * 256 + i];
    __syncthreads();

    float val = 0.0f;
    if (tid < NS) {
        val = b3[tid];
        const float* __restrict__ w = W3 + (size_t)tid * 256;
        #pragma unroll 8
        for (int u = 0; u < 256; ++u) val = fmaf(z_sm[u], w[u], val);
        v_sm[tid] = val;
    }
    __syncthreads();
    if (tid == 0) {
        float m = -1e30f;
        for (int i = 0; i < NS; ++i) m = fmaxf(m, v_sm[i]);
        red[0] = m;
    }
    __syncthreads();
    float e = 0.0f;
    if (tid < NS) { e = __expf(val - red[0]); v_sm[tid] = e; }
    __syncthreads();
    if (tid == 0) {
        float s = 0.0f;
        for (int i = 0; i < NS; ++i) s += v_sm[i];
        red[1] = __fdividef(1.0f, s);
    }
    __syncthreads();
    if (tid < NS) out[b * NS + tid] = e * red[1];
}

// ---------------------------------------------------------------------------
extern "C" void kernel_launch(void* const* d_in, const int* in_sizes, int n_in,
                              void* d_out, int out_size)
{
    const float* x    = (const float*)d_in[0];
    const float* Wih  = (const float*)d_in[1];
    const float* Whh  = (const float*)d_in[2];
    const float* bih  = (const float*)d_in[3];
    const float* bhh  = (const float*)d_in[4];
    const float* wlin = (const float*)d_in[5];
    const float* blin = (const float*)d_in[6];
    const float* W2   = (const float*)d_in[7];
    const float* b2   = (const float*)d_in[8];
    const float* W3   = (const float*)d_in[9];
    const float* b3   = (const float*)d_in[10];
    float* out = (float*)d_out;

    lstm_kernel<<<NBLK, NTHR>>>(x, Wih, Whh, bih, bhh, wlin, blin);
    sort_kernel<<<BATCH, 128>>>();
    mlp1_kernel<<<BATCH, 256>>>(W2, b2);
    mlp2_kernel<<<BATCH, 128>>>(W3, b3, out);
}

// round 4
// speedup vs baseline: 1.0165x; 1.0165x over previous
#include <cuda_runtime.h>
#include <cstdint>

// Problem constants
#define BATCH 64
#define TLEN  128
#define NS    100
#define AD    16
#define HD    120
#define G4    480          // 4*HD
#define KTOT  136          // HD + AD
#define NSEQ  (BATCH * NS) // 6400
#define TAU_INV 0.2f

// LSTM kernel tiling
#define SEQ_PB 48
#define NBLK   ((NSEQ + SEQ_PB - 1) / SEQ_PB)   // 134
#define NTHR   480                               // 16 seq-groups x 30 unit-quads
#define NPAIR  240                               // 480 gate-rows as 240 pairs

// Scratch (device globals; no dynamic allocation allowed)
__device__ float g_s[NSEQ];                    // scores per sequence
__device__ float g_phat[BATCH * NS * NS];      // relaxed permutation matrices
__device__ float g_z1[BATCH * 256];            // MLP hidden
// Packed weights: g_wpack[k][pair] = (W[r0][k], W[r1][k]); k<120 -> Whh, else Wih.
// Pair P = jq*8 + q*2 + h  ->  rows r0 = q*120 + 4*jq + 2*h, r1 = r0+1.
__device__ __align__(16) float2 g_wpack[KTOT][NPAIR];   // 261 KB, L2-resident

typedef unsigned long long ull;
union UF2 { ull u; float2 f; };

__device__ __forceinline__ ull fma2(ull a, ull b, ull c) {
    ull d;
    asm("fma.rn.f32x2 %0, %1, %2, %3;" : "=l"(d) : "l"(a), "l"(b), "l"(c));
    return d;
}

__device__ __forceinline__ float sigf(float x) {
    return __fdividef(1.0f, 1.0f + __expf(-x));
}
__device__ __forceinline__ float tanhf_fast(float x) {
    return 2.0f * __fdividef(1.0f, 1.0f + __expf(-2.0f * x)) - 1.0f;
}

// ---------------------------------------------------------------------------
// Kernel 0: pack weights into pair-interleaved layout (once per launch).
// ---------------------------------------------------------------------------
__global__ void pack_kernel(const float* __restrict__ Wih,
                            const float* __restrict__ Whh)
{
    int idx = blockIdx.x * blockDim.x + threadIdx.x;  // over KTOT*NPAIR
    if (idx >= KTOT * NPAIR) return;
    int k = idx / NPAIR, P = idx % NPAIR;
    int jq = P >> 3, rem = P & 7, q = rem >> 1, h = rem & 1;
    int r0 = q * HD + 4 * jq + 2 * h;
    float w0, w1;
    if (k < HD) { w0 = Whh[r0 * HD + k];        w1 = Whh[(r0 + 1) * HD + k]; }
    else        { w0 = Wih[r0 * AD + (k - HD)]; w1 = Wih[(r0 + 1) * AD + (k - HD)]; }
    ((float2*)g_wpack)[idx] = make_float2(w0, w1);
}

// ---------------------------------------------------------------------------
// Kernel 1: LSTM over all 6400 sequences + score head.  Packed f32x2 FMAs.
// Block: 48 sequences, 480 threads.
//   sg = tid & 15 -> 3 seqs: sg, sg+16, sg+32
//   jq = tid >> 4 -> unit quad 4jq..4jq+3, all 4 gates (8 row-pairs)
// h state duplicated in SMEM (k-major, (h,h) pairs); c in registers.
// ---------------------------------------------------------------------------
#define SM_H   0
#define SM_X   (HD * 96 * 4)                    // 46080
#define SM_B   (SM_X + AD * 96 * 4)             // 52224
#define SM_TOT (SM_B + NPAIR * 8)               // 54144

__global__ void __launch_bounds__(NTHR, 1)
lstm_kernel(const float* __restrict__ x,
            const float* __restrict__ bih,
            const float* __restrict__ bhh,
            const float* __restrict__ wlin,
            const float* __restrict__ blin)
{
    extern __shared__ char smem[];
    float (*h_dup)[96] = (float(*)[96])(smem + SM_H);   // [120][96]
    float (*x_dup)[96] = (float(*)[96])(smem + SM_X);   // [16][96]
    float2* bias_pk    = (float2*)(smem + SM_B);        // [240]

    const int tid = threadIdx.x;
    const int sg  = tid & 15;
    const int jq  = tid >> 4;              // 0..29
    const int n0  = blockIdx.x * SEQ_PB;

    // zero h_dup + x_dup
    for (int i = tid; i < (HD + AD) * 96; i += NTHR) ((float*)smem)[i] = 0.0f;
    // bias pairs
    if (tid < NPAIR) {
        int P = tid, jj = P >> 3, rem = P & 7, q = rem >> 1, h = rem & 1;
        int r0 = q * HD + 4 * jj + 2 * h;
        bias_pk[P] = make_float2(bih[r0] + bhh[r0], bih[r0 + 1] + bhh[r0 + 1]);
    }

    // x loader setup (threads < 192)
    size_t xbase = 0; bool xvalid = false; int xl = 0, xa4 = 0;
    if (tid < 192) {
        xl  = tid >> 2;          // local seq 0..47
        xa4 = tid & 3;
        int n = n0 + xl;
        if (n < NSEQ) {
            int b = n / NS, st = n % NS;
            xbase = ((size_t)b * TLEN * NS + st) * AD + xa4 * 4;
            xvalid = true;
        }
    }

    float c[3][4];
    #pragma unroll
    for (int s = 0; s < 3; ++s)
        #pragma unroll
        for (int u = 0; u < 4; ++u) c[s][u] = 0.0f;

    const int col0 = 2 * sg, col1 = 2 * (sg + 16), col2 = 2 * (sg + 32);

    __syncthreads();

    for (int t = 0; t < TLEN; ++t) {
        // ---- load x_t, duplicated ----
        if (xvalid) {
            float4 v = *(const float4*)&x[xbase + (size_t)t * (NS * AD)];
            UF2 p;
            p.f = make_float2(v.x, v.x); *(ull*)&x_dup[xa4 * 4 + 0][2 * xl] = p.u;
            p.f = make_float2(v.y, v.y); *(ull*)&x_dup[xa4 * 4 + 1][2 * xl] = p.u;
            p.f = make_float2(v.z, v.z); *(ull*)&x_dup[xa4 * 4 + 2][2 * xl] = p.u;
            p.f = make_float2(v.w, v.w); *(ull*)&x_dup[xa4 * 4 + 3][2 * xl] = p.u;
        }

        // ---- init accumulators from bias pairs ----
        UF2 acc[3][8];
        #pragma unroll
        for (int p = 0; p < 8; ++p) {
            UF2 b; b.f = bias_pk[jq * 8 + p];
            acc[0][p] = b; acc[1][p] = b; acc[2][p] = b;
        }

        // ---- recurrent part: K = 120 over h_dup ----
        #pragma unroll 4
        for (int k = 0; k < HD; ++k) {
            const ulonglong2* wr = (const ulonglong2*)&g_wpack[k][jq * 8];
            ulonglong2 w01 = wr[0], w23 = wr[1], w45 = wr[2], w67 = wr[3];
            ull a0 = *(const ull*)&h_dup[k][col0];
            ull a1 = *(const ull*)&h_dup[k][col1];
            ull a2 = *(const ull*)&h_dup[k][col2];
            ull w[8] = {w01.x, w01.y, w23.x, w23.y, w45.x, w45.y, w67.x, w67.y};
            #pragma unroll
            for (int p = 0; p < 8; ++p) {
                acc[0][p].u = fma2(a0, w[p], acc[0][p].u);
                acc[1][p].u = fma2(a1, w[p], acc[1][p].u);
                acc[2][p].u = fma2(a2, w[p], acc[2][p].u);
            }
        }

        __syncthreads();   // x_dup ready; all h_dup reads done

        // ---- input part: K = 16 over x_dup ----
        #pragma unroll 4
        for (int k = 0; k < AD; ++k) {
            const ulonglong2* wr = (const ulonglong2*)&g_wpack[HD + k][jq * 8];
            ulonglong2 w01 = wr[0], w23 = wr[1], w45 = wr[2], w67 = wr[3];
            ull a0 = *(const ull*)&x_dup[k][col0];
            ull a1 = *(const ull*)&x_dup[k][col1];
            ull a2 = *(const ull*)&x_dup[k][col2];
            ull w[8] = {w01.x, w01.y, w23.x, w23.y, w45.x, w45.y, w67.x, w67.y};
            #pragma unroll
            for (int p = 0; p < 8; ++p) {
                acc[0][p].u = fma2(a0, w[p], acc[0][p].u);
                acc[1][p].u = fma2(a1, w[p], acc[1][p].u);
                acc[2][p].u = fma2(a2, w[p], acc[2][p].u);
            }
        }

        // ---- activations + state update ----
        // pair p = q*2 + (u>>1); lane = u&1 selects unit 4jq+u
        #pragma unroll
        for (int s = 0; s < 3; ++s) {
            const int col = (s == 0) ? col0 : (s == 1) ? col1 : col2;
            #pragma unroll
            for (int u = 0; u < 4; ++u) {
                const int ph = u >> 1;
                float iv, fv, gv, ov;
                if (u & 1) {
                    iv = acc[s][0 + ph].f.y; fv = acc[s][2 + ph].f.y;
                    gv = acc[s][4 + ph].f.y; ov = acc[s][6 + ph].f.y;
                } else {
                    iv = acc[s][0 + ph].f.x; fv = acc[s][2 + ph].f.x;
                    gv = acc[s][4 + ph].f.x; ov = acc[s][6 + ph].f.x;
                }
                float ig = sigf(iv);
                float fg = sigf(fv);
                float gg = tanhf_fast(gv);
                float og = sigf(ov);
                float cn = fg * c[s][u] + ig * gg;
                c[s][u] = cn;
                float hv = og * tanhf_fast(cn);
                UF2 hd; hd.f = make_float2(hv, hv);
                *(ull*)&h_dup[4 * jq + u][col] = hd.u;
            }
        }
        __syncthreads();   // h_dup fully updated for next step
    }

    // ---- score head ----
    if (tid < SEQ_PB) {
        int n = n0 + tid;
        if (n < NSEQ) {
            float s = blin[0];
            #pragma unroll 4
            for (int j = 0; j < HD; ++j) s = fmaf(h_dup[j][2 * tid], wlin[j], s);
            g_s[n] = s;
        }
    }
}

// ---------------------------------------------------------------------------
// Kernel 2: NeuralSort relaxed permutation.
// ---------------------------------------------------------------------------
__global__ void sort_kernel()
{
    const int b   = blockIdx.x;
    const int tid = threadIdx.x;
    __shared__ float s_sm[NS];
    __shared__ float rs_sm[NS];

    if (tid < NS) s_sm[tid] = g_s[b * NS + tid];
    __syncthreads();

    if (tid < NS) {
        float si = s_sm[tid], r = 0.0f;
        #pragma unroll 4
        for (int j = 0; j < NS; ++j) r += fabsf(si - s_sm[j]);
        rs_sm[tid] = r;
    }
    __syncthreads();

    const int warp = tid >> 5, lane = tid & 31;
    for (int r = warp; r < NS; r += 4) {
        float scal = 99.0f - 2.0f * (float)r;
        float v[4];
        float mx = -1e30f;
        #pragma unroll
        for (int i = 0; i < 4; ++i) {
            int cidx = lane + i * 32;
            v[i] = (cidx < NS) ? (s_sm[cidx] * scal - rs_sm[cidx]) * TAU_INV : -1e30f;
            mx = fmaxf(mx, v[i]);
        }
        #pragma unroll
        for (int o = 16; o; o >>= 1) mx = fmaxf(mx, __shfl_xor_sync(0xffffffffu, mx, o));
        float sum = 0.0f;
        #pragma unroll
        for (int i = 0; i < 4; ++i) {
            int cidx = lane + i * 32;
            v[i] = (cidx < NS) ? __expf(v[i] - mx) : 0.0f;
            sum += v[i];
        }
        #pragma unroll
        for (int o = 16; o; o >>= 1) sum += __shfl_xor_sync(0xffffffffu, sum, o);
        float inv = __fdividef(1.0f, sum);
        #pragma unroll
        for (int i = 0; i < 4; ++i) {
            int cidx = lane + i * 32;
            if (cidx < NS) g_phat[((size_t)b * NS + r) * NS + cidx] = v[i] * inv;
        }
    }
}

// ---------------------------------------------------------------------------
// Kernel 3: z1 = relu(p_hat_flat @ W2^T + b2).
// ---------------------------------------------------------------------------
__global__ void mlp1_kernel(const float* __restrict__ W2,
                            const float* __restrict__ b2)
{
    const int b   = blockIdx.x;
    const int tid = threadIdx.x;   // 256
    const int warp = tid >> 5, lane = tid & 31;
    __shared__ float p_sm[NS * NS];   // 40000 B

    const float* __restrict__ pr = g_phat + (size_t)b * (NS * NS);
    for (int i = tid; i < NS * NS; i += 256) p_sm[i] = pr[i];
    __syncthreads();

    for (int u = warp; u < 256; u += 8) {
        const float* __restrict__ w = W2 + (size_t)u * (NS * NS);
        float acc = 0.0f;
        for (int m = lane * 4; m < NS * NS; m += 32 * 4) {
            float4 wv = *(const float4*)&w[m];
            float4 pv = *(const float4*)&p_sm[m];
            acc = fmaf(wv.x, pv.x, acc);
            acc = fmaf(wv.y, pv.y, acc);
            acc = fmaf(wv.z, pv.z, acc);
            acc = fmaf(wv.w, pv.w, acc);
        }
        #pragma unroll
        for (int o = 16; o; o >>= 1) acc += __shfl_xor_sync(0xffffffffu, acc, o);
        if (lane == 0) g_z1[b * 256 + u] = fmaxf(acc + b2[u], 0.0f);
    }
}

// ---------------------------------------------------------------------------
// Kernel 4: out = softmax(z1 @ W3^T + b3).
// ---------------------------------------------------------------------------
__global__ void mlp2_kernel(const float* __restrict__ W3,
                            const float* __restrict__ b3,
                            float* __restrict__ out)
{
    const int b   = blockIdx.x;
    const int tid = threadIdx.x;   // 128
    __shared__ float z_sm[256];
    __shared__ float v_sm[NS];
    __shared__ float red[2];

    for (int i = tid; i < 256; i += 128) z_sm[i] = g_z1[b * 256 + i];
    __syncthreads();

    float val = 0.0f;
    if (tid < NS) {
        val = b3[tid];
        const float* __restrict__ w = W3 + (size_t)tid * 256;
        #pragma unroll 8
        for (int u = 0; u < 256; ++u) val = fmaf(z_sm[u], w[u], val);
        v_sm[tid] = val;
    }
    __syncthreads();
    if (tid == 0) {
        float m = -1e30f;
        for (int i = 0; i < NS; ++i) m = fmaxf(m, v_sm[i]);
        red[0] = m;
    }
    __syncthreads();
    float e = 0.0f;
    if (tid < NS) { e = __expf(val - red[0]); v_sm[tid] = e; }
    __syncthreads();
    if (tid == 0) {
        float s = 0.0f;
        for (int i = 0; i < NS; ++i) s += v_sm[i];
        red[1] = __fdividef(1.0f, s);
    }
    __syncthreads();
    if (tid < NS) out[b * NS + tid] = e * red[1];
}

// ---------------------------------------------------------------------------
extern "C" void kernel_launch(void* const* d_in, const int* in_sizes, int n_in,
                              void* d_out, int out_size)
{
    const float* x    = (const float*)d_in[0];
    const float* Wih  = (const float*)d_in[1];
    const float* Whh  = (const float*)d_in[2];
    const float* bih  = (const float*)d_in[3];
    const float* bhh  = (const float*)d_in[4];
    const float* wlin = (const float*)d_in[5];
    const float* blin = (const float*)d_in[6];
    const float* W2   = (const float*)d_in[7];
    const float* b2   = (const float*)d_in[8];
    const float* W3   = (const float*)d_in[9];
    const float* b3   = (const float*)d_in[10];
    float* out = (float*)d_out;

    static bool attr_set = false;
    if (!attr_set) {
        cudaFuncSetAttribute(lstm_kernel,
                             cudaFuncAttributeMaxDynamicSharedMemorySize, SM_TOT);
        attr_set = true;
    }

    pack_kernel<<<(KTOT * NPAIR + 255) / 256, 256>>>(Wih, Whh);
    lstm_kernel<<<NBLK, NTHR, SM_TOT>>>(x, bih, bhh, wlin, blin);
    sort_kernel<<<BATCH, 128>>>();
    mlp1_kernel<<<BATCH, 256>>>(W2, b2);
    mlp2_kernel<<<BATCH, 128>>>(W3, b3, out);
}

// round 5
// speedup vs baseline: 1.0586x; 1.0415x over previous
#include <cuda_runtime.h>
#include <cstdint>

// Problem constants
#define BATCH 64
#define TLEN  128
#define NS    100
#define AD    16
#define HD    120
#define G4    480          // 4*HD
#define KTOT  136          // HD + AD
#define NSEQ  (BATCH * NS) // 6400
#define TAU_INV 0.2f

// LSTM kernel tiling
#define SEQ_PB 48
#define NBLK   ((NSEQ + SEQ_PB - 1) / SEQ_PB)   // 134
#define NTHR   480                               // 16 seq-groups x 30 unit-quads
#define NPAIR  240                               // 480 gate-rows as 240 pairs

// Scratch (device globals; no dynamic allocation allowed)
__device__ float g_s[NSEQ];                    // scores per sequence
__device__ float g_phat[BATCH * NS * NS];      // relaxed permutation matrices
__device__ float g_z1[BATCH * 256];            // MLP hidden
// Packed weights: g_wpack[k][pair] = (W[r0][k], W[r1][k]); k<120 -> Whh, else Wih.
__device__ __align__(16) float2 g_wpack[KTOT][NPAIR];   // 261 KB, L2-resident

typedef unsigned long long ull;
union UF2 { ull u; float2 f; };

__device__ __forceinline__ ull fma2(ull a, ull b, ull c) {
    ull d;
    asm("fma.rn.f32x2 %0, %1, %2, %3;" : "=l"(d) : "l"(a), "l"(b), "l"(c));
    return d;
}

__device__ __forceinline__ float sigf(float x) {
    return __fdividef(1.0f, 1.0f + __expf(-x));
}
__device__ __forceinline__ float tanhf_fast(float x) {
    return 2.0f * __fdividef(1.0f, 1.0f + __expf(-2.0f * x)) - 1.0f;
}

// ---------------------------------------------------------------------------
// Kernel 0: pack weights into pair-interleaved layout (once per launch).
// ---------------------------------------------------------------------------
__global__ void pack_kernel(const float* __restrict__ Wih,
                            const float* __restrict__ Whh)
{
    int idx = blockIdx.x * blockDim.x + threadIdx.x;  // over KTOT*NPAIR
    if (idx >= KTOT * NPAIR) return;
    int k = idx / NPAIR, P = idx % NPAIR;
    int jq = P >> 3, rem = P & 7, q = rem >> 1, h = rem & 1;
    int r0 = q * HD + 4 * jq + 2 * h;
    float w0, w1;
    if (k < HD) { w0 = Whh[r0 * HD + k];        w1 = Whh[(r0 + 1) * HD + k]; }
    else        { w0 = Wih[r0 * AD + (k - HD)]; w1 = Wih[(r0 + 1) * AD + (k - HD)]; }
    ((float2*)g_wpack)[idx] = make_float2(w0, w1);
}

// ---------------------------------------------------------------------------
// Kernel 1: LSTM over all 6400 sequences + score head (unchanged from R4;
// measured at the fp32 FMA roofline).
// ---------------------------------------------------------------------------
#define SM_H   0
#define SM_X   (HD * 96 * 4)                    // 46080
#define SM_B   (SM_X + AD * 96 * 4)             // 52224
#define SM_TOT (SM_B + NPAIR * 8)               // 54144

__global__ void __launch_bounds__(NTHR, 1)
lstm_kernel(const float* __restrict__ x,
            const float* __restrict__ bih,
            const float* __restrict__ bhh,
            const float* __restrict__ wlin,
            const float* __restrict__ blin)
{
    extern __shared__ char smem[];
    float (*h_dup)[96] = (float(*)[96])(smem + SM_H);   // [120][96]
    float (*x_dup)[96] = (float(*)[96])(smem + SM_X);   // [16][96]
    float2* bias_pk    = (float2*)(smem + SM_B);        // [240]

    const int tid = threadIdx.x;
    const int sg  = tid & 15;
    const int jq  = tid >> 4;              // 0..29
    const int n0  = blockIdx.x * SEQ_PB;

    for (int i = tid; i < (HD + AD) * 96; i += NTHR) ((float*)smem)[i] = 0.0f;
    if (tid < NPAIR) {
        int P = tid, jj = P >> 3, rem = P & 7, q = rem >> 1, h = rem & 1;
        int r0 = q * HD + 4 * jj + 2 * h;
        bias_pk[P] = make_float2(bih[r0] + bhh[r0], bih[r0 + 1] + bhh[r0 + 1]);
    }

    size_t xbase = 0; bool xvalid = false; int xl = 0, xa4 = 0;
    if (tid < 192) {
        xl  = tid >> 2;
        xa4 = tid & 3;
        int n = n0 + xl;
        if (n < NSEQ) {
            int b = n / NS, st = n % NS;
            xbase = ((size_t)b * TLEN * NS + st) * AD + xa4 * 4;
            xvalid = true;
        }
    }

    float c[3][4];
    #pragma unroll
    for (int s = 0; s < 3; ++s)
        #pragma unroll
        for (int u = 0; u < 4; ++u) c[s][u] = 0.0f;

    const int col0 = 2 * sg, col1 = 2 * (sg + 16), col2 = 2 * (sg + 32);

    __syncthreads();

    for (int t = 0; t < TLEN; ++t) {
        if (xvalid) {
            float4 v = *(const float4*)&x[xbase + (size_t)t * (NS * AD)];
            UF2 p;
            p.f = make_float2(v.x, v.x); *(ull*)&x_dup[xa4 * 4 + 0][2 * xl] = p.u;
            p.f = make_float2(v.y, v.y); *(ull*)&x_dup[xa4 * 4 + 1][2 * xl] = p.u;
            p.f = make_float2(v.z, v.z); *(ull*)&x_dup[xa4 * 4 + 2][2 * xl] = p.u;
            p.f = make_float2(v.w, v.w); *(ull*)&x_dup[xa4 * 4 + 3][2 * xl] = p.u;
        }

        UF2 acc[3][8];
        #pragma unroll
        for (int p = 0; p < 8; ++p) {
            UF2 b; b.f = bias_pk[jq * 8 + p];
            acc[0][p] = b; acc[1][p] = b; acc[2][p] = b;
        }

        #pragma unroll 4
        for (int k = 0; k < HD; ++k) {
            const ulonglong2* wr = (const ulonglong2*)&g_wpack[k][jq * 8];
            ulonglong2 w01 = wr[0], w23 = wr[1], w45 = wr[2], w67 = wr[3];
            ull a0 = *(const ull*)&h_dup[k][col0];
            ull a1 = *(const ull*)&h_dup[k][col1];
            ull a2 = *(const ull*)&h_dup[k][col2];
            ull w[8] = {w01.x, w01.y, w23.x, w23.y, w45.x, w45.y, w67.x, w67.y};
            #pragma unroll
            for (int p = 0; p < 8; ++p) {
                acc[0][p].u = fma2(a0, w[p], acc[0][p].u);
                acc[1][p].u = fma2(a1, w[p], acc[1][p].u);
                acc[2][p].u = fma2(a2, w[p], acc[2][p].u);
            }
        }

        __syncthreads();

        #pragma unroll 4
        for (int k = 0; k < AD; ++k) {
            const ulonglong2* wr = (const ulonglong2*)&g_wpack[HD + k][jq * 8];
            ulonglong2 w01 = wr[0], w23 = wr[1], w45 = wr[2], w67 = wr[3];
            ull a0 = *(const ull*)&x_dup[k][col0];
            ull a1 = *(const ull*)&x_dup[k][col1];
            ull a2 = *(const ull*)&x_dup[k][col2];
            ull w[8] = {w01.x, w01.y, w23.x, w23.y, w45.x, w45.y, w67.x, w67.y};
            #pragma unroll
            for (int p = 0; p < 8; ++p) {
                acc[0][p].u = fma2(a0, w[p], acc[0][p].u);
                acc[1][p].u = fma2(a1, w[p], acc[1][p].u);
                acc[2][p].u = fma2(a2, w[p], acc[2][p].u);
            }
        }

        #pragma unroll
        for (int s = 0; s < 3; ++s) {
            const int col = (s == 0) ? col0 : (s == 1) ? col1 : col2;
            #pragma unroll
            for (int u = 0; u < 4; ++u) {
                const int ph = u >> 1;
                float iv, fv, gv, ov;
                if (u & 1) {
                    iv = acc[s][0 + ph].f.y; fv = acc[s][2 + ph].f.y;
                    gv = acc[s][4 + ph].f.y; ov = acc[s][6 + ph].f.y;
                } else {
                    iv = acc[s][0 + ph].f.x; fv = acc[s][2 + ph].f.x;
                    gv = acc[s][4 + ph].f.x; ov = acc[s][6 + ph].f.x;
                }
                float ig = sigf(iv);
                float fg = sigf(fv);
                float gg = tanhf_fast(gv);
                float og = sigf(ov);
                float cn = fg * c[s][u] + ig * gg;
                c[s][u] = cn;
                float hv = og * tanhf_fast(cn);
                UF2 hd; hd.f = make_float2(hv, hv);
                *(ull*)&h_dup[4 * jq + u][col] = hd.u;
            }
        }
        __syncthreads();
    }

    if (tid < SEQ_PB) {
        int n = n0 + tid;
        if (n < NSEQ) {
            float s = blin[0];
            #pragma unroll 4
            for (int j = 0; j < HD; ++j) s = fmaf(h_dup[j][2 * tid], wlin[j], s);
            g_s[n] = s;
        }
    }
}

// ---------------------------------------------------------------------------
// Kernel 2: NeuralSort relaxed permutation (unchanged).
// ---------------------------------------------------------------------------
__global__ void sort_kernel()
{
    const int b   = blockIdx.x;
    const int tid = threadIdx.x;
    __shared__ float s_sm[NS];
    __shared__ float rs_sm[NS];

    if (tid < NS) s_sm[tid] = g_s[b * NS + tid];
    __syncthreads();

    if (tid < NS) {
        float si = s_sm[tid], r = 0.0f;
        #pragma unroll 4
        for (int j = 0; j < NS; ++j) r += fabsf(si - s_sm[j]);
        rs_sm[tid] = r;
    }
    __syncthreads();

    const int warp = tid >> 5, lane = tid & 31;
    for (int r = warp; r < NS; r += 4) {
        float scal = 99.0f - 2.0f * (float)r;
        float v[4];
        float mx = -1e30f;
        #pragma unroll
        for (int i = 0; i < 4; ++i) {
            int cidx = lane + i * 32;
            v[i] = (cidx < NS) ? (s_sm[cidx] * scal - rs_sm[cidx]) * TAU_INV : -1e30f;
            mx = fmaxf(mx, v[i]);
        }
        #pragma unroll
        for (int o = 16; o; o >>= 1) mx = fmaxf(mx, __shfl_xor_sync(0xffffffffu, mx, o));
        float sum = 0.0f;
        #pragma unroll
        for (int i = 0; i < 4; ++i) {
            int cidx = lane + i * 32;
            v[i] = (cidx < NS) ? __expf(v[i] - mx) : 0.0f;
            sum += v[i];
        }
        #pragma unroll
        for (int o = 16; o; o >>= 1) sum += __shfl_xor_sync(0xffffffffu, sum, o);
        float inv = __fdividef(1.0f, sum);
        #pragma unroll
        for (int i = 0; i < 4; ++i) {
            int cidx = lane + i * 32;
            if (cidx < NS) g_phat[((size_t)b * NS + r) * NS + cidx] = v[i] * inv;
        }
    }
}

// ---------------------------------------------------------------------------
// Kernel 3: z1 = relu(p_hat_flat @ W2^T + b2).  REWRITTEN:
// grid = (64 batches, 4 unit-tiles of 64).  256 threads = 8 warps.
// p_hat[b] staged in smem (reused by 64 units); warp-per-unit, unrolled
// float4 dot -> high MLP, latency hidden.  W2 L2 traffic = 4x10MB = 41MB.
// ---------------------------------------------------------------------------
__global__ void __launch_bounds__(256)
mlp1_kernel(const float* __restrict__ W2,
            const float* __restrict__ b2)
{
    const int b    = blockIdx.x;
    const int ug   = blockIdx.y;           // unit tile: units ug*64 .. +63
    const int tid  = threadIdx.x;          // 256
    const int warp = tid >> 5, lane = tid & 31;
    __shared__ float p_sm[NS * NS];        // 40000 B

    // stage p_hat[b] with float4 loads
    const float4* __restrict__ pr4 = (const float4*)(g_phat + (size_t)b * (NS * NS));
    for (int i = tid; i < (NS * NS) / 4; i += 256)
        ((float4*)p_sm)[i] = pr4[i];
    __syncthreads();

    #pragma unroll 1
    for (int i = 0; i < 8; ++i) {
        const int u = ug * 64 + warp * 8 + i;
        const float* __restrict__ w = W2 + (size_t)u * (NS * NS);
        float acc = 0.0f;
        // 10000 floats = 2500 float4; 78 full rounds of 32 lanes + 4 tail
        int m = lane * 4;
        #pragma unroll 4
        for (int r = 0; r < 78; ++r, m += 128) {
            float4 wv = *(const float4*)&w[m];
            float4 pv = *(const float4*)&p_sm[m];
            acc = fmaf(wv.x, pv.x, acc);
            acc = fmaf(wv.y, pv.y, acc);
            acc = fmaf(wv.z, pv.z, acc);
            acc = fmaf(wv.w, pv.w, acc);
        }
        if (lane < 4) {   // tail: float4s 2496..2499
            float4 wv = *(const float4*)&w[m];
            float4 pv = *(const float4*)&p_sm[m];
            acc = fmaf(wv.x, pv.x, acc);
            acc = fmaf(wv.y, pv.y, acc);
            acc = fmaf(wv.z, pv.z, acc);
            acc = fmaf(wv.w, pv.w, acc);
        }
        #pragma unroll
        for (int o = 16; o; o >>= 1) acc += __shfl_xor_sync(0xffffffffu, acc, o);
        if (lane == 0) g_z1[b * 256 + u] = fmaxf(acc + b2[u], 0.0f);
    }
}

// ---------------------------------------------------------------------------
// Kernel 4: out = softmax(z1 @ W3^T + b3).  REWRITTEN: warp-per-output dot.
// ---------------------------------------------------------------------------
__global__ void __launch_bounds__(256)
mlp2_kernel(const float* __restrict__ W3,
            const float* __restrict__ b3,
            float* __restrict__ out)
{
    const int b   = blockIdx.x;
    const int tid = threadIdx.x;   // 256 = 8 warps
    const int warp = tid >> 5, lane = tid & 31;
    __shared__ float z_sm[256];
    __shared__ float v_sm[NS];
    __shared__ float red[2];

    if (tid < 256) z_sm[tid] = g_z1[b * 256 + tid];
    __syncthreads();

    // 100 outputs over 8 warps
    for (int o = warp; o < NS; o += 8) {
        const float* __restrict__ w = W3 + (size_t)o * 256;
        // 256 = 32 lanes x 8: each lane 2 float4
        float4 w0 = *(const float4*)&w[lane * 8];
        float4 w1 = *(const float4*)&w[lane * 8 + 4];
        const float* z = &z_sm[lane * 8];
        float acc = w0.x * z[0] + w0.y * z[1] + w0.z * z[2] + w0.w * z[3]
                  + w1.x * z[4] + w1.y * z[5] + w1.z * z[6] + w1.w * z[7];
        #pragma unroll
        for (int off = 16; off; off >>= 1) acc += __shfl_xor_sync(0xffffffffu, acc, off);
        if (lane == 0) v_sm[o] = acc + b3[o];
    }
    __syncthreads();

    if (tid == 0) {
        float m = -1e30f;
        for (int i = 0; i < NS; ++i) m = fmaxf(m, v_sm[i]);
        red[0] = m;
    }
    __syncthreads();
    float e = 0.0f;
    if (tid < NS) { e = __expf(v_sm[tid] - red[0]); v_sm[tid] = e; }
    __syncthreads();
    if (tid == 0) {
        float s = 0.0f;
        for (int i = 0; i < NS; ++i) s += v_sm[i];
        red[1] = __fdividef(1.0f, s);
    }
    __syncthreads();
    if (tid < NS) out[b * NS + tid] = e * red[1];
}

// ---------------------------------------------------------------------------
extern "C" void kernel_launch(void* const* d_in, const int* in_sizes, int n_in,
                              void* d_out, int out_size)
{
    const float* x    = (const float*)d_in[0];
    const float* Wih  = (const float*)d_in[1];
    const float* Whh  = (const float*)d_in[2];
    const float* bih  = (const float*)d_in[3];
    const float* bhh  = (const float*)d_in[4];
    const float* wlin = (const float*)d_in[5];
    const float* blin = (const float*)d_in[6];
    const float* W2   = (const float*)d_in[7];
    const float* b2   = (const float*)d_in[8];
    const float* W3   = (const float*)d_in[9];
    const float* b3   = (const float*)d_in[10];
    float* out = (float*)d_out;

    static bool attr_set = false;
    if (!attr_set) {
        cudaFuncSetAttribute(lstm_kernel,
                             cudaFuncAttributeMaxDynamicSharedMemorySize, SM_TOT);
        attr_set = true;
    }

    pack_kernel<<<(KTOT * NPAIR + 255) / 256, 256>>>(Wih, Whh);
    lstm_kernel<<<NBLK, NTHR, SM_TOT>>>(x, bih, bhh, wlin, blin);
    sort_kernel<<<BATCH, 128>>>();
    mlp1_kernel<<<dim3(BATCH, 4), 256>>>(W2, b2);
    mlp2_kernel<<<BATCH, 256>>>(W3, b3, out);
}